// round 9
// baseline (speedup 1.0000x reference)
#include <cuda_runtime.h>
#include <cstdint>

#define NC 512
#define BATCH 128

// ---------------- device scratch (no allocation allowed) ----------------
__device__ int g_sym0[BATCH * 32 * 32];
__device__ int g_x1[BATCH * 14 * 14 * 6];
__device__ int g_x2[BATCH * 5 * 5 * 16];
__device__ int g_x3[BATCH * 120];
__device__ int g_x4[BATCH * 84];
__device__ __align__(16) unsigned short g_addlut16[NC * NC];          // u16 add_lut
__device__ __align__(16) unsigned short g_arr1[BATCH * 400 * 120];    // fc1 sorted seqs
__device__ __align__(16) unsigned short g_arr2[BATCH * 120 * 84];     // fc2 sorted seqs

extern __shared__ unsigned int dyn_smem[];

// ---------------- Kernel 0: convert add_lut to u16 ----------------
__global__ void k_cvt(const int* __restrict__ add_lut) {
    int i = blockIdx.x * blockDim.x + threadIdx.x;
    if (i < NC * NC) g_addlut16[i] = (unsigned short)add_lut[i];
}

// ---------------- Kernel A: discretize ----------------
__global__ void k_discretize(const float* __restrict__ x,
                             const float* __restrict__ cent) {
    __shared__ float sc[NC];
    for (int i = threadIdx.x; i < NC; i += blockDim.x) sc[i] = cent[i];
    __syncthreads();
    int idx = blockIdx.x * blockDim.x + threadIdx.x;
    if (idx >= BATCH * 32 * 32) return;
    float px = x[idx];
    float best = fabsf(px - sc[0]);
    int bi = 0;
#pragma unroll 8
    for (int i = 1; i < NC; i++) {
        float d = fabsf(px - sc[i]);
        if (d < best) { best = d; bi = i; }
    }
    g_sym0[idx] = bi;
}

// ---------------- Kernel B: conv1 (n=25) ----------------
#define C1_ROWS (BATCH * 14 * 14 * 6)
#define C1_T 256
__global__ __launch_bounds__(C1_T)
void k_conv1(const int* __restrict__ conv_lut, const int* __restrict__ add_lut,
             const int* __restrict__ c1f, const int* __restrict__ bias,
             const int* __restrict__ relu) {
    __shared__ unsigned short arr[25 * C1_T];
    __shared__ int sw[25 * 6];
    for (int i = threadIdx.x; i < 150; i += blockDim.x) sw[i] = c1f[i];
    __syncthreads();
    int row = blockIdx.x * C1_T + threadIdx.x;
    if (row >= C1_ROWS) return;
    int tid = threadIdx.x;
    int co = row % 6;
    int t = row / 6;
    int ow = t % 14; t /= 14;
    int oh = t % 14;
    int b = t / 14;

#define A1(j) arr[(j) * C1_T + tid]
    const int* base = g_sym0 + b * 1024 + (oh * 2) * 32 + (ow * 2);
    int i = 0;
    for (int di = 0; di < 5; di++)
        for (int dj = 0; dj < 5; dj++) {
            int win = base[di * 32 + dj];
            int g = conv_lut[win * NC + sw[i * 6 + co]];
            A1(i) = (unsigned short)g;
            i++;
        }
    for (int ii = 1; ii < 25; ii++) {
        unsigned short key = A1(ii);
        int j = ii - 1;
        while (j >= 0 && A1(j) > key) { A1(j + 1) = A1(j); j--; }
        A1(j + 1) = key;
    }
    int tmp = A1(0);
    for (int j = 1; j < 25; j++) {
        int xv = A1(j);
        int t2 = add_lut[xv * NC + tmp];
        if (j < 23) {
            int nxt = A1(j + 1);
            if (t2 > nxt) {
                int p = j + 1;
                while (p + 1 < 25) {
                    unsigned short nx = A1(p + 1);
                    if ((int)nx < t2) { A1(p) = nx; p++; }
                    else break;
                }
                A1(p) = (unsigned short)t2;
                tmp = nxt;
            } else tmp = t2;
        } else tmp = t2;
    }
    g_x1[row] = relu[bias[tmp * 6 + co]];
#undef A1
}

// ---------------- Kernel C: conv2 (n=150) hist+bitmap PQ, u16 LUT chain ----------------
#define C2_ROWS (BATCH * 5 * 5 * 16)
#define C2_T 256
__global__ __launch_bounds__(C2_T, 1)
void k_conv2(const int* __restrict__ conv_lut,
             const int* __restrict__ c2f, const int* __restrict__ bias,
             const int* __restrict__ relu) {
    unsigned int* bm = dyn_smem;              // 16*T words
    unsigned int* hw = dyn_smem + 16 * C2_T;  // 128*T words (512 u8 / thread)
    int tid = threadIdx.x;
    int row = blockIdx.x * C2_T + tid;
    if (row >= C2_ROWS) return;

    for (int k = 0; k < 16; k++) bm[k * C2_T + tid] = 0;
    for (int k = 0; k < 128; k++) hw[k * C2_T + tid] = 0;

    int co = row % 16;
    int t = row / 16;
    int ow = t % 5; t /= 5;
    int oh = t % 5;
    int b = t / 5;

    const int* base = g_x1 + ((b * 14 + oh * 2) * 14 + ow * 2) * 6;
    int i = 0;
    for (int di = 0; di < 5; di++)
        for (int dj = 0; dj < 5; dj++) {
            const int* p = base + (di * 14 + dj) * 6;
#pragma unroll
            for (int c = 0; c < 6; c++) {
                int win = p[c];
                int g = conv_lut[win * NC + c2f[i * 16 + co]];
                unsigned char* bp =
                    (unsigned char*)(hw + ((g >> 2) * C2_T + tid)) + (g & 3);
                *bp = (unsigned char)(*bp + 1);
                bm[(g >> 5) * C2_T + tid] |= 1u << (g & 31);
                i++;
            }
        }

    int wi = 0;
    auto peek = [&](unsigned int& w) -> int {
        w = bm[wi * C2_T + tid];
        while (w == 0 && wi < 15) { wi++; w = bm[wi * C2_T + tid]; }
        return wi * 32 + (__ffs((int)w) - 1);
    };
    auto dec = [&](int v, unsigned int w) {
        unsigned char* bp =
            (unsigned char*)(hw + ((v >> 2) * C2_T + tid)) + (v & 3);
        unsigned char c = *bp; c--; *bp = c;
        if (c == 0) bm[(v >> 5) * C2_T + tid] = w & ~(1u << (v & 31));
    };

    unsigned int w;
    int v = peek(w); dec(v, w);
    int tmp = v;
    const int n = 150;
    for (int j = 1; j < n; j++) {
        v = peek(w); dec(v, w);
        int t2 = (int)__ldg(&g_addlut16[(v << 9) + tmp]);
        if (j < n - 2) {
            unsigned int w2;
            int nxt = peek(w2);
            if (t2 > nxt) {
                dec(nxt, w2);
                unsigned char* bp =
                    (unsigned char*)(hw + ((t2 >> 2) * C2_T + tid)) + (t2 & 3);
                *bp = (unsigned char)(*bp + 1);
                bm[(t2 >> 5) * C2_T + tid] |= 1u << (t2 & 31);
                tmp = nxt;
            } else tmp = t2;
        } else tmp = t2;
    }
    g_x2[row] = relu[bias[tmp * 16 + co]];
}

// ---------------- fc1 build: hist -> counting-sort -> global staging ----------------
#define FC1_T 120
#define FC1_N 400
__global__ __launch_bounds__(FC1_T, 1)
void k_fc1_build(const int* __restrict__ fc_lut, const int* __restrict__ f1f) {
    // smem: xr[400] int | hist u16[512][120]
    int* xr = (int*)dyn_smem;
    unsigned short* hist = (unsigned short*)(xr + FC1_N);
    int tid = threadIdx.x;
    int b = blockIdx.x;

    for (int i = tid; i < FC1_N; i += FC1_T) {
        int c = i / 25;
        int r = i % 25;
        xr[i] = g_x2[((b * 5 + r / 5) * 5 + (r % 5)) * 16 + c];
    }
    {
        unsigned int* hz = (unsigned int*)hist;
        for (int i = tid; i < NC * FC1_T / 2; i += FC1_T) hz[i] = 0;
    }
    __syncthreads();

    const int4* wrow4 = (const int4*)(f1f + tid * FC1_N);
    for (int i0 = 0; i0 < FC1_N; i0 += 8) {
        int4 wa = wrow4[i0 >> 2];
        int4 wb = wrow4[(i0 >> 2) + 1];
        int wv[8] = {wa.x, wa.y, wa.z, wa.w, wb.x, wb.y, wb.z, wb.w};
        int g[8];
#pragma unroll
        for (int k = 0; k < 8; k++)
            g[k] = __ldg(&fc_lut[(xr[i0 + k] << 9) + wv[k]]);
#pragma unroll
        for (int k = 0; k < 8; k++) hist[g[k] * FC1_T + tid]++;
    }
    // counting-sort expansion directly to global staging (ascending order)
    unsigned short* dst = g_arr1 + b * (FC1_N * FC1_T) + tid;
    int p = 0;
    for (int v = 0; v < NC; v++) {
        int c = hist[v * FC1_T + tid];
        while (c--) { dst[p * FC1_T] = (unsigned short)v; p++; }
    }
}

// ---------------- fc1 fold: NO smem -> full L1 caches add_lut band ----------------
__global__ __launch_bounds__(FC1_T)
void k_fc1_fold(const int* __restrict__ bias, const int* __restrict__ relu) {
    int tid = threadIdx.x;
    int b = blockIdx.x;
    const unsigned short* a = g_arr1 + b * (FC1_N * FC1_T) + tid;
    int tmp = (int)__ldg(&a[0]);
#pragma unroll 4
    for (int i = 1; i < FC1_N; i++) {
        int v = (int)__ldg(&a[i * FC1_T]);
        tmp = (int)__ldg(&g_addlut16[(v << 9) + tmp]);
    }
    g_x3[b * 120 + tid] = relu[bias[tmp * 120 + tid]];
}

// ---------------- fc2 build ----------------
#define FC2_T 84
#define FC2_N 120
__global__ __launch_bounds__(FC2_T, 1)
void k_fc2_build(const int* __restrict__ fc_lut, const int* __restrict__ f2f) {
    // smem: xr[120] int | hist u8[512][84]
    int* xr = (int*)dyn_smem;
    unsigned char* hist = (unsigned char*)(xr + FC2_N);
    int tid = threadIdx.x;
    int b = blockIdx.x;

    for (int i = tid; i < FC2_N; i += FC2_T) xr[i] = g_x3[b * 120 + i];
    {
        unsigned int* hz = (unsigned int*)hist;
        for (int i = tid; i < NC * FC2_T / 4; i += FC2_T) hz[i] = 0;
    }
    __syncthreads();

    const int4* wrow4 = (const int4*)(f2f + tid * FC2_N);
    for (int i0 = 0; i0 < FC2_N; i0 += 8) {
        int4 wa = wrow4[i0 >> 2];
        int4 wb = wrow4[(i0 >> 2) + 1];
        int wv[8] = {wa.x, wa.y, wa.z, wa.w, wb.x, wb.y, wb.z, wb.w};
        int g[8];
#pragma unroll
        for (int k = 0; k < 8; k++)
            g[k] = __ldg(&fc_lut[(xr[i0 + k] << 9) + wv[k]]);
#pragma unroll
        for (int k = 0; k < 8; k++) hist[g[k] * FC2_T + tid]++;
    }
    unsigned short* dst = g_arr2 + b * (FC2_N * FC2_T) + tid;
    int p = 0;
    for (int v = 0; v < NC; v++) {
        int c = hist[v * FC2_T + tid];
        while (c--) { dst[p * FC2_T] = (unsigned short)v; p++; }
    }
}

// ---------------- fc2 fold ----------------
__global__ __launch_bounds__(FC2_T)
void k_fc2_fold(const int* __restrict__ bias, const int* __restrict__ relu) {
    int tid = threadIdx.x;
    int b = blockIdx.x;
    const unsigned short* a = g_arr2 + b * (FC2_N * FC2_T) + tid;
    int tmp = (int)__ldg(&a[0]);
#pragma unroll 4
    for (int i = 1; i < FC2_N; i++) {
        int v = (int)__ldg(&a[i * FC2_T]);
        tmp = (int)__ldg(&g_addlut16[(v << 9) + tmp]);
    }
    g_x4[b * 84 + tid] = relu[bias[tmp * 84 + tid]];
}

// ---------------- Kernel F: head ----------------
__global__ void k_head(const float* __restrict__ cent,
                       const float* __restrict__ w,
                       const float* __restrict__ bvec,
                       float* __restrict__ out) {
    int b = blockIdx.x * blockDim.x + threadIdx.x;
    if (b >= BATCH) return;
    float f[84];
#pragma unroll
    for (int i = 0; i < 84; i++) f[i] = cent[g_x4[b * 84 + i]];
    float lg[10];
    float mx = -1e30f;
#pragma unroll
    for (int k = 0; k < 10; k++) {
        float s = bvec[k];
#pragma unroll
        for (int i = 0; i < 84; i++) s += f[i] * w[k * 84 + i];
        lg[k] = s;
        mx = fmaxf(mx, s);
    }
    float sum = 0.f;
#pragma unroll
    for (int k = 0; k < 10; k++) { lg[k] = __expf(lg[k] - mx); sum += lg[k]; }
    float inv = 1.f / sum;
#pragma unroll
    for (int k = 0; k < 10; k++) out[b * 10 + k] = lg[k] * inv;
}

// ---------------- launch ----------------
extern "C" void kernel_launch(void* const* d_in, const int* in_sizes, int n_in,
                              void* d_out, int out_size) {
    const float* x_bat   = (const float*)d_in[0];
    const float* cent    = (const float*)d_in[1];
    const int* conv_lut  = (const int*)d_in[2];
    const int* fc_lut    = (const int*)d_in[3];
    const int* add_lut   = (const int*)d_in[4];
    const int* relu_lut  = (const int*)d_in[5];
    const int* c1_bias   = (const int*)d_in[6];
    const int* c2_bias   = (const int*)d_in[7];
    const int* f1_bias   = (const int*)d_in[8];
    const int* f2_bias   = (const int*)d_in[9];
    const int* c1f       = (const int*)d_in[10];
    const int* c2f       = (const int*)d_in[11];
    const int* f1f       = (const int*)d_in[12];
    const int* f2f       = (const int*)d_in[13];
    const float* fc3_w   = (const float*)d_in[14];
    const float* fc3_b   = (const float*)d_in[15];
    float* out           = (float*)d_out;

    size_t c2_smem  = (size_t)(16 + 128) * C2_T * 4;                 // 147456
    size_t f1b_smem = (size_t)FC1_N * 4 + (size_t)NC * FC1_T * 2;    // 124480
    size_t f2b_smem = (size_t)FC2_N * 4 + (size_t)NC * FC2_T;        //  43488
    cudaFuncSetAttribute(k_conv2, cudaFuncAttributeMaxDynamicSharedMemorySize,
                         (int)c2_smem);
    cudaFuncSetAttribute(k_fc1_build,
                         cudaFuncAttributeMaxDynamicSharedMemorySize,
                         (int)f1b_smem);
    cudaFuncSetAttribute(k_fc2_build,
                         cudaFuncAttributeMaxDynamicSharedMemorySize,
                         (int)f2b_smem);

    k_cvt<<<(NC * NC + 255) / 256, 256>>>(add_lut);
    k_discretize<<<(BATCH * 32 * 32 + 255) / 256, 256>>>(x_bat, cent);
    k_conv1<<<(C1_ROWS + C1_T - 1) / C1_T, C1_T>>>(conv_lut, add_lut, c1f,
                                                   c1_bias, relu_lut);
    k_conv2<<<(C2_ROWS + C2_T - 1) / C2_T, C2_T, c2_smem>>>(conv_lut, c2f,
                                                            c2_bias, relu_lut);
    k_fc1_build<<<BATCH, FC1_T, f1b_smem>>>(fc_lut, f1f);
    k_fc1_fold<<<BATCH, FC1_T>>>(f1_bias, relu_lut);
    k_fc2_build<<<BATCH, FC2_T, f2b_smem>>>(fc_lut, f2f);
    k_fc2_fold<<<BATCH, FC2_T>>>(f2_bias, relu_lut);
    k_head<<<1, BATCH>>>(cent, fc3_w, fc3_b, out);
}

// round 11
// speedup vs baseline: 1.3112x; 1.3112x over previous
#include <cuda_runtime.h>
#include <cstdint>

#define NC 512
#define BATCH 128

// ---------------- device scratch (no allocation allowed) ----------------
__device__ int g_sym0[BATCH * 32 * 32];
__device__ int g_x1[BATCH * 14 * 14 * 6];
__device__ int g_x2[BATCH * 5 * 5 * 16];
__device__ int g_x3[BATCH * 120];
__device__ int g_x4[BATCH * 84];
__device__ __align__(16) unsigned short g_addlut16[NC * NC];        // u16 add_lut
__device__ __align__(16) unsigned short g_arr1[BATCH * 400 * 120];  // fc1 staging

extern __shared__ unsigned int dyn_smem[];

// ---------------- Kernel 0: convert add_lut to u16 ----------------
__global__ void k_cvt(const int* __restrict__ add_lut) {
    int i = blockIdx.x * blockDim.x + threadIdx.x;
    if (i < NC * NC) g_addlut16[i] = (unsigned short)add_lut[i];
}

// ---------------- Kernel A: discretize ----------------
__global__ void k_discretize(const float* __restrict__ x,
                             const float* __restrict__ cent) {
    __shared__ float sc[NC];
    for (int i = threadIdx.x; i < NC; i += blockDim.x) sc[i] = cent[i];
    __syncthreads();
    int idx = blockIdx.x * blockDim.x + threadIdx.x;
    if (idx >= BATCH * 32 * 32) return;
    float px = x[idx];
    float best = fabsf(px - sc[0]);
    int bi = 0;
#pragma unroll 8
    for (int i = 1; i < NC; i++) {
        float d = fabsf(px - sc[i]);
        if (d < best) { best = d; bi = i; }
    }
    g_sym0[idx] = bi;
}

// ---------------- Kernel B: conv1 (n=25) ----------------
#define C1_ROWS (BATCH * 14 * 14 * 6)
#define C1_T 256
__global__ __launch_bounds__(C1_T)
void k_conv1(const int* __restrict__ conv_lut, const int* __restrict__ add_lut,
             const int* __restrict__ c1f, const int* __restrict__ bias,
             const int* __restrict__ relu) {
    __shared__ unsigned short arr[25 * C1_T];
    __shared__ int sw[25 * 6];
    for (int i = threadIdx.x; i < 150; i += blockDim.x) sw[i] = c1f[i];
    __syncthreads();
    int row = blockIdx.x * C1_T + threadIdx.x;
    if (row >= C1_ROWS) return;
    int tid = threadIdx.x;
    int co = row % 6;
    int t = row / 6;
    int ow = t % 14; t /= 14;
    int oh = t % 14;
    int b = t / 14;

#define A1(j) arr[(j) * C1_T + tid]
    const int* base = g_sym0 + b * 1024 + (oh * 2) * 32 + (ow * 2);
    int i = 0;
    for (int di = 0; di < 5; di++)
        for (int dj = 0; dj < 5; dj++) {
            int win = base[di * 32 + dj];
            int g = conv_lut[win * NC + sw[i * 6 + co]];
            A1(i) = (unsigned short)g;
            i++;
        }
    for (int ii = 1; ii < 25; ii++) {
        unsigned short key = A1(ii);
        int j = ii - 1;
        while (j >= 0 && A1(j) > key) { A1(j + 1) = A1(j); j--; }
        A1(j + 1) = key;
    }
    int tmp = A1(0);
    for (int j = 1; j < 25; j++) {
        int xv = A1(j);
        int t2 = add_lut[xv * NC + tmp];
        if (j < 23) {
            int nxt = A1(j + 1);
            if (t2 > nxt) {
                int p = j + 1;
                while (p + 1 < 25) {
                    unsigned short nx = A1(p + 1);
                    if ((int)nx < t2) { A1(p) = nx; p++; }
                    else break;
                }
                A1(p) = (unsigned short)t2;
                tmp = nxt;
            } else tmp = t2;
        } else tmp = t2;
    }
    g_x1[row] = relu[bias[tmp * 6 + co]];
#undef A1
}

// ---------------- Kernel C: conv2 (n=150) hist+bitmap PQ, T=384 single wave ----------------
#define C2_ROWS (BATCH * 5 * 5 * 16)
#define C2_T 384
__global__ __launch_bounds__(C2_T, 1)
void k_conv2(const int* __restrict__ conv_lut,
             const int* __restrict__ c2f, const int* __restrict__ bias,
             const int* __restrict__ relu) {
    unsigned int* bm = dyn_smem;              // 16*T words
    unsigned int* hw = dyn_smem + 16 * C2_T;  // 128*T words (512 u8 / thread)
    int tid = threadIdx.x;
    int row = blockIdx.x * C2_T + tid;
    if (row >= C2_ROWS) return;

    for (int k = 0; k < 16; k++) bm[k * C2_T + tid] = 0;
    for (int k = 0; k < 128; k++) hw[k * C2_T + tid] = 0;

    int co = row % 16;
    int t = row / 16;
    int ow = t % 5; t /= 5;
    int oh = t % 5;
    int b = t / 5;

    const int* base = g_x1 + ((b * 14 + oh * 2) * 14 + ow * 2) * 6;
    int i = 0;
    for (int di = 0; di < 5; di++)
        for (int dj = 0; dj < 5; dj++) {
            const int* p = base + (di * 14 + dj) * 6;
#pragma unroll
            for (int c = 0; c < 6; c++) {
                int win = p[c];
                int g = conv_lut[win * NC + c2f[i * 16 + co]];
                unsigned char* bp =
                    (unsigned char*)(hw + ((g >> 2) * C2_T + tid)) + (g & 3);
                *bp = (unsigned char)(*bp + 1);
                bm[(g >> 5) * C2_T + tid] |= 1u << (g & 31);
                i++;
            }
        }

    int wi = 0;
    auto peek = [&](unsigned int& w) -> int {
        w = bm[wi * C2_T + tid];
        while (w == 0 && wi < 15) { wi++; w = bm[wi * C2_T + tid]; }
        return wi * 32 + (__ffs((int)w) - 1);
    };
    auto dec = [&](int v, unsigned int w) {
        unsigned char* bp =
            (unsigned char*)(hw + ((v >> 2) * C2_T + tid)) + (v & 3);
        unsigned char c = *bp; c--; *bp = c;
        if (c == 0) bm[(v >> 5) * C2_T + tid] = w & ~(1u << (v & 31));
    };

    unsigned int w;
    int v = peek(w); dec(v, w);
    int tmp = v;
    const int n = 150;
    for (int j = 1; j < n; j++) {
        v = peek(w); dec(v, w);
        int t2 = (int)__ldg(&g_addlut16[(v << 9) + tmp]);
        if (j < n - 2) {
            unsigned int w2;
            int nxt = peek(w2);
            if (t2 > nxt) {
                dec(nxt, w2);
                unsigned char* bp =
                    (unsigned char*)(hw + ((t2 >> 2) * C2_T + tid)) + (t2 & 3);
                *bp = (unsigned char)(*bp + 1);
                bm[(t2 >> 5) * C2_T + tid] |= 1u << (t2 & 31);
                tmp = nxt;
            } else tmp = t2;
        } else tmp = t2;
    }
    g_x2[row] = relu[bias[tmp * 16 + co]];
}

// ---------------- fc1 build: hist -> expand in smem -> COALESCED dump ----------------
#define FC1_T 120
#define FC1_N 400
// smem: xr[400] int (1600B) | hist u16[512][120] (122880B) | arr u16[400][120] (96000B)
__global__ __launch_bounds__(FC1_T, 1)
void k_fc1_build(const int* __restrict__ fc_lut, const int* __restrict__ f1f) {
    int* xr = (int*)dyn_smem;
    unsigned short* hist = (unsigned short*)(xr + FC1_N);
    unsigned short* arr = hist + NC * FC1_T;
    int tid = threadIdx.x;
    int b = blockIdx.x;

    for (int i = tid; i < FC1_N; i += FC1_T) {
        int c = i / 25;
        int r = i % 25;
        xr[i] = g_x2[((b * 5 + r / 5) * 5 + (r % 5)) * 16 + c];
    }
    {
        unsigned int* hz = (unsigned int*)hist;
        for (int i = tid; i < NC * FC1_T / 2; i += FC1_T) hz[i] = 0;
    }
    __syncthreads();

    const int4* wrow4 = (const int4*)(f1f + tid * FC1_N);
    for (int i0 = 0; i0 < FC1_N; i0 += 8) {
        int4 wa = wrow4[i0 >> 2];
        int4 wb = wrow4[(i0 >> 2) + 1];
        int wv[8] = {wa.x, wa.y, wa.z, wa.w, wb.x, wb.y, wb.z, wb.w};
        int g[8];
#pragma unroll
        for (int k = 0; k < 8; k++)
            g[k] = __ldg(&fc_lut[(xr[i0 + k] << 9) + wv[k]]);
#pragma unroll
        for (int k = 0; k < 8; k++) hist[g[k] * FC1_T + tid]++;
    }
    // counting-sort expansion into smem arr (ascending per thread)
    {
        int p = 0;
        for (int v = 0; v < NC; v++) {
            int c = hist[v * FC1_T + tid];
            while (c--) arr[(p++) * FC1_T + tid] = (unsigned short)v;
        }
    }
    __syncthreads();
    // coalesced u32 dump of arr to global staging (identical layout)
    const unsigned int* asrc = (const unsigned int*)arr;
    unsigned int* adst = (unsigned int*)(g_arr1 + (size_t)b * (FC1_N * FC1_T));
    for (int i = tid; i < FC1_N * FC1_T / 2; i += FC1_T) adst[i] = asrc[i];
}

// ---------------- fc1 fold: ZERO smem -> full 228KB L1 for add_lut band ----------------
__global__ __launch_bounds__(FC1_T)
void k_fc1_fold(const int* __restrict__ bias, const int* __restrict__ relu) {
    int tid = threadIdx.x;
    int b = blockIdx.x;
    const unsigned short* a = g_arr1 + (size_t)b * (FC1_N * FC1_T) + tid;
    int tmp = (int)__ldg(&a[0]);
#pragma unroll 4
    for (int i = 1; i < FC1_N; i++) {
        int v = (int)__ldg(&a[i * FC1_T]);
        tmp = (int)__ldg(&g_addlut16[(v << 9) + tmp]);
    }
    g_x3[b * 120 + tid] = relu[bias[tmp * 120 + tid]];
}

// ---------------- fc2: merged build+fold (smem ~64KB leaves ~160KB L1) ----------------
#define FC2_T 84
#define FC2_N 120
// smem: xr[120] int (480B) | hist u8[512][84] (43008B) | arr u16[120][84] (20160B)
__global__ __launch_bounds__(FC2_T, 1)
void k_fc2(const int* __restrict__ fc_lut, const int* __restrict__ f2f,
           const int* __restrict__ bias, const int* __restrict__ relu) {
    int* xr = (int*)dyn_smem;
    unsigned char* hist = (unsigned char*)(xr + FC2_N);
    unsigned short* arr = (unsigned short*)(hist + NC * FC2_T);
    int tid = threadIdx.x;
    int b = blockIdx.x;

    for (int i = tid; i < FC2_N; i += FC2_T) xr[i] = g_x3[b * 120 + i];
    {
        unsigned int* hz = (unsigned int*)hist;
        for (int i = tid; i < NC * FC2_T / 4; i += FC2_T) hz[i] = 0;
    }
    __syncthreads();

    const int4* wrow4 = (const int4*)(f2f + tid * FC2_N);
    for (int i0 = 0; i0 < FC2_N; i0 += 8) {
        int4 wa = wrow4[i0 >> 2];
        int4 wb = wrow4[(i0 >> 2) + 1];
        int wv[8] = {wa.x, wa.y, wa.z, wa.w, wb.x, wb.y, wb.z, wb.w};
        int g[8];
#pragma unroll
        for (int k = 0; k < 8; k++)
            g[k] = __ldg(&fc_lut[(xr[i0 + k] << 9) + wv[k]]);
#pragma unroll
        for (int k = 0; k < 8; k++) hist[g[k] * FC2_T + tid]++;
    }
    {
        int p = 0;
        for (int v = 0; v < NC; v++) {
            int c = hist[v * FC2_T + tid];
            while (c--) arr[(p++) * FC2_T + tid] = (unsigned short)v;
        }
    }
    // uniform fold from smem arr; chain loads hit L1 (band-resident u16 LUT)
    int tmp = (int)arr[tid];
#pragma unroll 4
    for (int i = 1; i < FC2_N; i++) {
        int v = (int)arr[i * FC2_T + tid];
        tmp = (int)__ldg(&g_addlut16[(v << 9) + tmp]);
    }
    g_x4[b * 84 + tid] = relu[bias[tmp * 84 + tid]];
}

// ---------------- Kernel F: head ----------------
__global__ void k_head(const float* __restrict__ cent,
                       const float* __restrict__ w,
                       const float* __restrict__ bvec,
                       float* __restrict__ out) {
    int b = blockIdx.x * blockDim.x + threadIdx.x;
    if (b >= BATCH) return;
    float f[84];
#pragma unroll
    for (int i = 0; i < 84; i++) f[i] = cent[g_x4[b * 84 + i]];
    float lg[10];
    float mx = -1e30f;
#pragma unroll
    for (int k = 0; k < 10; k++) {
        float s = bvec[k];
#pragma unroll
        for (int i = 0; i < 84; i++) s += f[i] * w[k * 84 + i];
        lg[k] = s;
        mx = fmaxf(mx, s);
    }
    float sum = 0.f;
#pragma unroll
    for (int k = 0; k < 10; k++) { lg[k] = __expf(lg[k] - mx); sum += lg[k]; }
    float inv = 1.f / sum;
#pragma unroll
    for (int k = 0; k < 10; k++) out[b * 10 + k] = lg[k] * inv;
}

// ---------------- launch ----------------
extern "C" void kernel_launch(void* const* d_in, const int* in_sizes, int n_in,
                              void* d_out, int out_size) {
    const float* x_bat   = (const float*)d_in[0];
    const float* cent    = (const float*)d_in[1];
    const int* conv_lut  = (const int*)d_in[2];
    const int* fc_lut    = (const int*)d_in[3];
    const int* add_lut   = (const int*)d_in[4];
    const int* relu_lut  = (const int*)d_in[5];
    const int* c1_bias   = (const int*)d_in[6];
    const int* c2_bias   = (const int*)d_in[7];
    const int* f1_bias   = (const int*)d_in[8];
    const int* f2_bias   = (const int*)d_in[9];
    const int* c1f       = (const int*)d_in[10];
    const int* c2f       = (const int*)d_in[11];
    const int* f1f       = (const int*)d_in[12];
    const int* f2f       = (const int*)d_in[13];
    const float* fc3_w   = (const float*)d_in[14];
    const float* fc3_b   = (const float*)d_in[15];
    float* out           = (float*)d_out;

    size_t c2_smem  = (size_t)(16 + 128) * C2_T * 4;                 // 221184
    size_t f1b_smem = (size_t)FC1_N * 4 + (size_t)NC * FC1_T * 2
                    + (size_t)FC1_N * FC1_T * 2;                     // 220480
    size_t f2_smem  = (size_t)FC2_N * 4 + (size_t)NC * FC2_T
                    + (size_t)FC2_N * FC2_T * 2;                     //  63648
    cudaFuncSetAttribute(k_conv2, cudaFuncAttributeMaxDynamicSharedMemorySize,
                         (int)c2_smem);
    cudaFuncSetAttribute(k_fc1_build,
                         cudaFuncAttributeMaxDynamicSharedMemorySize,
                         (int)f1b_smem);
    cudaFuncSetAttribute(k_fc2, cudaFuncAttributeMaxDynamicSharedMemorySize,
                         (int)f2_smem);

    k_cvt<<<(NC * NC + 255) / 256, 256>>>(add_lut);
    k_discretize<<<(BATCH * 32 * 32 + 255) / 256, 256>>>(x_bat, cent);
    k_conv1<<<(C1_ROWS + C1_T - 1) / C1_T, C1_T>>>(conv_lut, add_lut, c1f,
                                                   c1_bias, relu_lut);
    k_conv2<<<(C2_ROWS + C2_T - 1) / C2_T, C2_T, c2_smem>>>(conv_lut, c2f,
                                                            c2_bias, relu_lut);
    k_fc1_build<<<BATCH, FC1_T, f1b_smem>>>(fc_lut, f1f);
    k_fc1_fold<<<BATCH, FC1_T>>>(f1_bias, relu_lut);
    k_fc2<<<BATCH, FC2_T, f2_smem>>>(fc_lut, f2f, f2_bias, relu_lut);
    k_head<<<1, BATCH>>>(cent, fc3_w, fc3_b, out);
}

// round 14
// speedup vs baseline: 1.3709x; 1.0456x over previous
#include <cuda_runtime.h>
#include <cstdint>

#define NC 512
#define BATCH 128

// ---------------- device scratch (no allocation allowed) ----------------
__device__ int g_sym0[BATCH * 32 * 32];
__device__ int g_x1[BATCH * 14 * 14 * 6];
__device__ int g_x2[BATCH * 5 * 5 * 16];
__device__ int g_x3[BATCH * 120];
__device__ int g_x4[BATCH * 84];
__device__ __align__(16) unsigned short g_addlut16[NC * NC];        // u16 add_lut
__device__ __align__(16) unsigned short g_arr1[BATCH * 400 * 120];  // fc1 staging

extern __shared__ unsigned int dyn_smem[];

// ---------------- Kernel 0: convert add_lut to u16 ----------------
__global__ void k_cvt(const int* __restrict__ add_lut) {
    int i = blockIdx.x * blockDim.x + threadIdx.x;
    if (i < NC * NC) g_addlut16[i] = (unsigned short)add_lut[i];
}

// ---------------- Kernel A: discretize ----------------
__global__ void k_discretize(const float* __restrict__ x,
                             const float* __restrict__ cent) {
    __shared__ float sc[NC];
    for (int i = threadIdx.x; i < NC; i += blockDim.x) sc[i] = cent[i];
    __syncthreads();
    int idx = blockIdx.x * blockDim.x + threadIdx.x;
    if (idx >= BATCH * 32 * 32) return;
    float px = x[idx];
    float best = fabsf(px - sc[0]);
    int bi = 0;
#pragma unroll 8
    for (int i = 1; i < NC; i++) {
        float d = fabsf(px - sc[i]);
        if (d < best) { best = d; bi = i; }
    }
    g_sym0[idx] = bi;
}

// ---------------- Kernel B: conv1 (n=25), u16 chain LUT ----------------
#define C1_ROWS (BATCH * 14 * 14 * 6)
#define C1_T 256
__global__ __launch_bounds__(C1_T)
void k_conv1(const int* __restrict__ conv_lut,
             const int* __restrict__ c1f, const int* __restrict__ bias,
             const int* __restrict__ relu) {
    __shared__ unsigned short arr[25 * C1_T];
    __shared__ int sw[25 * 6];
    for (int i = threadIdx.x; i < 150; i += blockDim.x) sw[i] = c1f[i];
    __syncthreads();
    int row = blockIdx.x * C1_T + threadIdx.x;
    if (row >= C1_ROWS) return;
    int tid = threadIdx.x;
    int co = row % 6;
    int t = row / 6;
    int ow = t % 14; t /= 14;
    int oh = t % 14;
    int b = t / 14;

#define A1(j) arr[(j) * C1_T + tid]
    const int* base = g_sym0 + b * 1024 + (oh * 2) * 32 + (ow * 2);
    int i = 0;
    for (int di = 0; di < 5; di++)
        for (int dj = 0; dj < 5; dj++) {
            int win = base[di * 32 + dj];
            int g = conv_lut[win * NC + sw[i * 6 + co]];
            A1(i) = (unsigned short)g;
            i++;
        }
    for (int ii = 1; ii < 25; ii++) {
        unsigned short key = A1(ii);
        int j = ii - 1;
        while (j >= 0 && A1(j) > key) { A1(j + 1) = A1(j); j--; }
        A1(j + 1) = key;
    }
    int tmp = A1(0);
    for (int j = 1; j < 25; j++) {
        int xv = A1(j);
        int t2 = (int)__ldg(&g_addlut16[(xv << 9) + tmp]);
        if (j < 23) {
            int nxt = A1(j + 1);
            if (t2 > nxt) {
                int p = j + 1;
                while (p + 1 < 25) {
                    unsigned short nx = A1(p + 1);
                    if ((int)nx < t2) { A1(p) = nx; p++; }
                    else break;
                }
                A1(p) = (unsigned short)t2;
                tmp = nxt;
            } else tmp = t2;
        } else tmp = t2;
    }
    g_x1[row] = relu[bias[tmp * 6 + co]];
#undef A1
}

// ---------------- conv2 slow path (local memory, exact, ~never taken) ----------------
__device__ __noinline__ int conv2_slow(const int* __restrict__ base,
                                       const int* __restrict__ conv_lut,
                                       const int* __restrict__ c2f, int co) {
    unsigned char cnt[NC];
    unsigned int bmp[16];
#pragma unroll
    for (int k = 0; k < 16; k++) bmp[k] = 0;
    for (int k = 0; k < NC; k++) cnt[k] = 0;
    int i = 0;
    for (int di = 0; di < 5; di++)
        for (int dj = 0; dj < 5; dj++) {
            const int* p = base + (di * 14 + dj) * 6;
            for (int c = 0; c < 6; c++) {
                int g = conv_lut[p[c] * NC + c2f[i * 16 + co]];
                cnt[g]++;
                bmp[g >> 5] |= 1u << (g & 31);
                i++;
            }
        }
    int wi = 0;
    unsigned int w;
    auto peek = [&]() -> int {
        w = bmp[wi];
        while (w == 0 && wi < 15) { wi++; w = bmp[wi]; }
        return wi * 32 + (__ffs((int)w) - 1);
    };
    auto dec = [&](int v) {
        if (--cnt[v] == 0) bmp[v >> 5] &= ~(1u << (v & 31));
    };
    int v = peek(); dec(v);
    int tmp = v;
    for (int j = 1; j < 150; j++) {
        v = peek(); dec(v);
        int t2 = (int)__ldg(&g_addlut16[(v << 9) + tmp]);
        if (j < 148) {
            int nxt = peek();
            if (t2 > nxt) {
                dec(nxt);
                cnt[t2]++;
                bmp[t2 >> 5] |= 1u << (t2 & 31);
                tmp = nxt;
            } else tmp = t2;
        } else tmp = t2;
    }
    return tmp;
}

// ---------------- Kernel C: conv2 (n=150), NIBBLE counters -> 123KB smem, big L1 ----------------
#define C2_ROWS (BATCH * 5 * 5 * 16)
#define C2_T 384
__global__ __launch_bounds__(C2_T, 1)
void k_conv2(const int* __restrict__ conv_lut,
             const int* __restrict__ c2f, const int* __restrict__ bias,
             const int* __restrict__ relu) {
    unsigned int* bm = dyn_smem;              // 16 words/thread (512-bit bitmap)
    unsigned int* hw = dyn_smem + 16 * C2_T;  // 64 words/thread (512 u4 counters)
    int tid = threadIdx.x;
    int row = blockIdx.x * C2_T + tid;
    if (row >= C2_ROWS) return;

    for (int k = 0; k < 16; k++) bm[k * C2_T + tid] = 0;
    for (int k = 0; k < 64; k++) hw[k * C2_T + tid] = 0;

    int co = row % 16;
    int t = row / 16;
    int ow = t % 5; t /= 5;
    int oh = t % 5;
    int b = t / 5;

    const int* base = g_x1 + ((b * 14 + oh * 2) * 14 + ow * 2) * 6;
    bool ovf = false;

    auto inc = [&](int g) {
        int idx = (g >> 3) * C2_T + tid;
        int sh = (g & 7) * 4;
        unsigned int w0 = hw[idx];
        if (((w0 >> sh) & 15u) == 15u) ovf = true;
        hw[idx] = w0 + (1u << sh);
        bm[(g >> 5) * C2_T + tid] |= 1u << (g & 31);
    };

    int i = 0;
    for (int di = 0; di < 5; di++)
        for (int dj = 0; dj < 5; dj++) {
            const int* p = base + (di * 14 + dj) * 6;
#pragma unroll
            for (int c = 0; c < 6; c++) {
                int win = p[c];
                int g = conv_lut[win * NC + c2f[i * 16 + co]];
                inc(g);
                i++;
            }
        }

    int wi = 0;
    auto peek = [&](unsigned int& w) -> int {
        w = bm[wi * C2_T + tid];
        while (w == 0 && wi < 15) { wi++; w = bm[wi * C2_T + tid]; }
        return wi * 32 + (__ffs((int)w) - 1);
    };
    auto dec = [&](int v, unsigned int w) {
        int idx = (v >> 3) * C2_T + tid;
        int sh = (v & 7) * 4;
        unsigned int hv = hw[idx] - (1u << sh);
        hw[idx] = hv;
        if (((hv >> sh) & 15u) == 0u)
            bm[(v >> 5) * C2_T + tid] = w & ~(1u << (v & 31));
    };

    unsigned int w;
    int v = peek(w); dec(v, w);
    int tmp = v;
    const int n = 150;
    for (int j = 1; j < n; j++) {
        v = peek(w); dec(v, w);
        int t2 = (int)__ldg(&g_addlut16[(v << 9) + tmp]);
        if (j < n - 2) {
            unsigned int w2;
            int nxt = peek(w2);
            if (t2 > nxt) {
                dec(nxt, w2);
                inc(t2);
                tmp = nxt;
            } else tmp = t2;
        } else tmp = t2;
    }
    if (ovf) tmp = conv2_slow(base, conv_lut, c2f, co);  // exact fallback
    g_x2[row] = relu[bias[tmp * 16 + co]];
}

// ---------------- fc1 build: u8 hist -> expand in smem -> coalesced dump ----------------
#define FC1_T 120
#define FC1_N 400
// smem: xr[400] int (1600B) | hist u8[512][120] (61440B) | arr u16[400][120] (96000B)
__global__ __launch_bounds__(FC1_T, 1)
void k_fc1_build(const int* __restrict__ fc_lut, const int* __restrict__ f1f) {
    int* xr = (int*)dyn_smem;
    unsigned char* hist = (unsigned char*)(xr + FC1_N);
    unsigned short* arr = (unsigned short*)(hist + NC * FC1_T);
    int tid = threadIdx.x;
    int b = blockIdx.x;

    for (int i = tid; i < FC1_N; i += FC1_T) {
        int c = i / 25;
        int r = i % 25;
        xr[i] = g_x2[((b * 5 + r / 5) * 5 + (r % 5)) * 16 + c];
    }
    {
        unsigned int* hz = (unsigned int*)hist;
        for (int i = tid; i < NC * FC1_T / 4; i += FC1_T) hz[i] = 0;
    }
    __syncthreads();

    const int4* wrow4 = (const int4*)(f1f + tid * FC1_N);
    for (int i0 = 0; i0 < FC1_N; i0 += 8) {
        int4 wa = wrow4[i0 >> 2];
        int4 wb = wrow4[(i0 >> 2) + 1];
        int wv[8] = {wa.x, wa.y, wa.z, wa.w, wb.x, wb.y, wb.z, wb.w};
        int g[8];
#pragma unroll
        for (int k = 0; k < 8; k++)
            g[k] = __ldg(&fc_lut[(xr[i0 + k] << 9) + wv[k]]);
#pragma unroll
        for (int k = 0; k < 8; k++) hist[g[k] * FC1_T + tid]++;
    }
    // counting-sort expansion into smem arr (ascending per thread)
    {
        int p = 0;
        for (int v = 0; v < NC; v++) {
            int c = hist[v * FC1_T + tid];
            while (c--) arr[(p++) * FC1_T + tid] = (unsigned short)v;
        }
    }
    __syncthreads();
    // coalesced u32 dump of arr to global staging (identical layout)
    const unsigned int* asrc = (const unsigned int*)arr;
    unsigned int* adst = (unsigned int*)(g_arr1 + (size_t)b * (FC1_N * FC1_T));
    for (int i = tid; i < FC1_N * FC1_T / 2; i += FC1_T) adst[i] = asrc[i];
}

// ---------------- fc1 fold: ZERO smem -> full 228KB L1 for add_lut band ----------------
__global__ __launch_bounds__(FC1_T)
void k_fc1_fold(const int* __restrict__ bias, const int* __restrict__ relu) {
    int tid = threadIdx.x;
    int b = blockIdx.x;
    const unsigned short* a = g_arr1 + (size_t)b * (FC1_N * FC1_T) + tid;
    int tmp = (int)__ldg(&a[0]);
#pragma unroll 4
    for (int i = 1; i < FC1_N; i++) {
        int v = (int)__ldg(&a[i * FC1_T]);
        tmp = (int)__ldg(&g_addlut16[(v << 9) + tmp]);
    }
    g_x3[b * 120 + tid] = relu[bias[tmp * 120 + tid]];
}

// ---------------- fc2: merged build+fold (smem ~64KB leaves ~160KB L1) ----------------
#define FC2_T 84
#define FC2_N 120
__global__ __launch_bounds__(FC2_T, 1)
void k_fc2(const int* __restrict__ fc_lut, const int* __restrict__ f2f,
           const int* __restrict__ bias, const int* __restrict__ relu) {
    int* xr = (int*)dyn_smem;
    unsigned char* hist = (unsigned char*)(xr + FC2_N);
    unsigned short* arr = (unsigned short*)(hist + NC * FC2_T);
    int tid = threadIdx.x;
    int b = blockIdx.x;

    for (int i = tid; i < FC2_N; i += FC2_T) xr[i] = g_x3[b * 120 + i];
    {
        unsigned int* hz = (unsigned int*)hist;
        for (int i = tid; i < NC * FC2_T / 4; i += FC2_T) hz[i] = 0;
    }
    __syncthreads();

    const int4* wrow4 = (const int4*)(f2f + tid * FC2_N);
    for (int i0 = 0; i0 < FC2_N; i0 += 8) {
        int4 wa = wrow4[i0 >> 2];
        int4 wb = wrow4[(i0 >> 2) + 1];
        int wv[8] = {wa.x, wa.y, wa.z, wa.w, wb.x, wb.y, wb.z, wb.w};
        int g[8];
#pragma unroll
        for (int k = 0; k < 8; k++)
            g[k] = __ldg(&fc_lut[(xr[i0 + k] << 9) + wv[k]]);
#pragma unroll
        for (int k = 0; k < 8; k++) hist[g[k] * FC2_T + tid]++;
    }
    {
        int p = 0;
        for (int v = 0; v < NC; v++) {
            int c = hist[v * FC2_T + tid];
            while (c--) arr[(p++) * FC2_T + tid] = (unsigned short)v;
        }
    }
    int tmp = (int)arr[tid];
#pragma unroll 4
    for (int i = 1; i < FC2_N; i++) {
        int v = (int)arr[i * FC2_T + tid];
        tmp = (int)__ldg(&g_addlut16[(v << 9) + tmp]);
    }
    g_x4[b * 84 + tid] = relu[bias[tmp * 84 + tid]];
}

// ---------------- Kernel F: head ----------------
__global__ void k_head(const float* __restrict__ cent,
                       const float* __restrict__ w,
                       const float* __restrict__ bvec,
                       float* __restrict__ out) {
    int b = blockIdx.x * blockDim.x + threadIdx.x;
    if (b >= BATCH) return;
    float f[84];
#pragma unroll
    for (int i = 0; i < 84; i++) f[i] = cent[g_x4[b * 84 + i]];
    float lg[10];
    float mx = -1e30f;
#pragma unroll
    for (int k = 0; k < 10; k++) {
        float s = bvec[k];
#pragma unroll
        for (int i = 0; i < 84; i++) s += f[i] * w[k * 84 + i];
        lg[k] = s;
        mx = fmaxf(mx, s);
    }
    float sum = 0.f;
#pragma unroll
    for (int k = 0; k < 10; k++) { lg[k] = __expf(lg[k] - mx); sum += lg[k]; }
    float inv = 1.f / sum;
#pragma unroll
    for (int k = 0; k < 10; k++) out[b * 10 + k] = lg[k] * inv;
}

// ---------------- launch ----------------
extern "C" void kernel_launch(void* const* d_in, const int* in_sizes, int n_in,
                              void* d_out, int out_size) {
    const float* x_bat   = (const float*)d_in[0];
    const float* cent    = (const float*)d_in[1];
    const int* conv_lut  = (const int*)d_in[2];
    const int* fc_lut    = (const int*)d_in[3];
    const int* add_lut   = (const int*)d_in[4];
    const int* relu_lut  = (const int*)d_in[5];
    const int* c1_bias   = (const int*)d_in[6];
    const int* c2_bias   = (const int*)d_in[7];
    const int* f1_bias   = (const int*)d_in[8];
    const int* f2_bias   = (const int*)d_in[9];
    const int* c1f       = (const int*)d_in[10];
    const int* c2f       = (const int*)d_in[11];
    const int* f1f       = (const int*)d_in[12];
    const int* f2f       = (const int*)d_in[13];
    const float* fc3_w   = (const float*)d_in[14];
    const float* fc3_b   = (const float*)d_in[15];
    float* out           = (float*)d_out;

    size_t c2_smem  = (size_t)(16 + 64) * C2_T * 4;                  // 122880
    size_t f1b_smem = (size_t)FC1_N * 4 + (size_t)NC * FC1_T
                    + (size_t)FC1_N * FC1_T * 2;                     // 159040
    size_t f2_smem  = (size_t)FC2_N * 4 + (size_t)NC * FC2_T
                    + (size_t)FC2_N * FC2_T * 2;                     //  63648
    cudaFuncSetAttribute(k_conv2, cudaFuncAttributeMaxDynamicSharedMemorySize,
                         (int)c2_smem);
    cudaFuncSetAttribute(k_fc1_build,
                         cudaFuncAttributeMaxDynamicSharedMemorySize,
                         (int)f1b_smem);
    cudaFuncSetAttribute(k_fc2, cudaFuncAttributeMaxDynamicSharedMemorySize,
                         (int)f2_smem);

    k_cvt<<<(NC * NC + 255) / 256, 256>>>(add_lut);
    k_discretize<<<(BATCH * 32 * 32 + 255) / 256, 256>>>(x_bat, cent);
    k_conv1<<<(C1_ROWS + C1_T - 1) / C1_T, C1_T>>>(conv_lut, c1f,
                                                   c1_bias, relu_lut);
    k_conv2<<<(C2_ROWS + C2_T - 1) / C2_T, C2_T, c2_smem>>>(conv_lut, c2f,
                                                            c2_bias, relu_lut);
    k_fc1_build<<<BATCH, FC1_T, f1b_smem>>>(fc_lut, f1f);
    k_fc1_fold<<<BATCH, FC1_T>>>(f1_bias, relu_lut);
    k_fc2<<<BATCH, FC2_T, f2_smem>>>(fc_lut, f2f, f2_bias, relu_lut);
    k_head<<<1, BATCH>>>(cent, fc3_w, fc3_b, out);
}